// round 9
// baseline (speedup 1.0000x reference)
#include <cuda_runtime.h>
#include <cuda_bf16.h>
#include <math.h>
#include <stdint.h>

// expm(S) for 4096 skew-symmetric 64x64 matrices.
// Scaling & squaring (s=4), degree-9 Paterson-Stockmeyer, 9 matmuls of 64^3.
// mma.sync.m16n8k16 bf16 split hi/lo (3 products), fp32 accumulate.
// One matrix per CTA, FIVE CTAs/SM: smem cut to 43 KB by storing only the
// scaled input vector w = v/16 and reconstructing B[r][c] by triangular
// indexing; registers cut under 102 by dropping the A-fragment keep cache.

#define LDO 136     // operand pitch in bf16 elems (272 B -> conflict-free LDSM)

#define SM_X   0        // X buffer: 64 rows x [hi 64 | lo 64] bf16 -> 17408 B
#define SM_B2  17408    // B2 buffer (A operand for the PS chain)   -> 17408 B
#define SM_V   34816    // w = v/16, 2016 floats -> 8064 B (pad 8192)
#define SMEM_BYTES 43008

static __device__ __forceinline__ uint32_t smem_u32(const void* p) {
    uint32_t a;
    asm("{ .reg .u64 t; cvta.to.shared.u64 t, %1; cvt.u32.u64 %0, t; }" : "=r"(a) : "l"(p));
    return a;
}
static __device__ __forceinline__ void ldsm4(uint32_t* r, uint32_t a) {
    asm volatile("ldmatrix.sync.aligned.m8n8.x4.shared.b16 {%0,%1,%2,%3}, [%4];"
        : "=r"(r[0]), "=r"(r[1]), "=r"(r[2]), "=r"(r[3]) : "r"(a));
}
static __device__ __forceinline__ void ldsm4t(uint32_t* r, uint32_t a) {
    asm volatile("ldmatrix.sync.aligned.m8n8.x4.trans.shared.b16 {%0,%1,%2,%3}, [%4];"
        : "=r"(r[0]), "=r"(r[1]), "=r"(r[2]), "=r"(r[3]) : "r"(a));
}
static __device__ __forceinline__ void mma16816(float* c, const uint32_t* a, const uint32_t* b) {
    asm volatile("mma.sync.aligned.m16n8k16.row.col.f32.bf16.bf16.f32 "
        "{%0,%1,%2,%3}, {%4,%5,%6,%7}, {%8,%9}, {%0,%1,%2,%3};"
        : "+f"(c[0]), "+f"(c[1]), "+f"(c[2]), "+f"(c[3])
        : "r"(a[0]), "r"(a[1]), "r"(a[2]), "r"(a[3]), "r"(b[0]), "r"(b[1]));
}
// hw = bf16x2(x1,x0), lw = bf16x2 of residuals
static __device__ __forceinline__ void splitw(float x0, float x1, uint32_t& hw, uint32_t& lw) {
    asm("cvt.rn.bf16x2.f32 %0, %1, %2;" : "=r"(hw) : "f"(x1), "f"(x0));
    float h0 = __uint_as_float(hw << 16);
    float h1 = __uint_as_float(hw & 0xffff0000u);
    float r0 = x0 - h0, r1 = x1 - h1;
    asm("cvt.rn.bf16x2.f32 %0, %1, %2;" : "=r"(lw) : "f"(r1), "f"(r0));
}
// B[row][col] = S[row][col]/16 from w = v/16 (strict-upper row-major vector).
static __device__ __forceinline__ float getB(const float* w, int row, int col) {
    if (col > row) return -w[row * (127 - row) / 2 - row - 1 + col];
    if (col < row) return  w[col * (127 - col) / 2 - col - 1 + row];
    return 0.f;
}

// 3-product MMA block for one k-tile: c += Ah*Bh + Ah*Bl + Al*Bh
static __device__ __forceinline__ void prod_all(
    float c[2][4][4],
    const uint32_t* ah0, const uint32_t* ah1,
    const uint32_t* al0, const uint32_t* al1,
    uint32_t bh[2][4], uint32_t bl[2][4])
{
#pragma unroll
    for (int t = 0; t < 2; t++) {
        mma16816(c[0][2 * t],     ah0, bh[t]);
        mma16816(c[0][2 * t + 1], ah0, bh[t] + 2);
        mma16816(c[1][2 * t],     ah1, bh[t]);
        mma16816(c[1][2 * t + 1], ah1, bh[t] + 2);
        mma16816(c[0][2 * t],     ah0, bl[t]);
        mma16816(c[0][2 * t + 1], ah0, bl[t] + 2);
        mma16816(c[1][2 * t],     ah1, bl[t]);
        mma16816(c[1][2 * t + 1], ah1, bl[t] + 2);
        mma16816(c[0][2 * t],     al0, bh[t]);
        mma16816(c[0][2 * t + 1], al0, bh[t] + 2);
        mma16816(c[1][2 * t],     al1, bh[t]);
        mma16816(c[1][2 * t + 1], al1, bh[t] + 2);
    }
}

// C(64x64) = A * B. A row-major via ldmatrix, B row-major via ldmatrix.trans.
static __device__ __forceinline__ void mm_compute(
    float c[2][4][4], uint32_t aBase, uint32_t bBase, int wid, int lid)
{
#pragma unroll
    for (int m = 0; m < 2; m++)
#pragma unroll
        for (int j = 0; j < 4; j++)
#pragma unroll
            for (int q = 0; q < 4; q++) c[m][j][q] = 0.f;

    const int r0 = (wid >> 1) * 32, c0 = (wid & 1) * 32;
    const uint32_t aA = aBase + (uint32_t)((r0 + (lid & 15)) * LDO + (lid >> 4) * 8) * 2;
    const uint32_t bA = bBase
        + (uint32_t)(((lid & 7) + ((lid & 8) ? 8 : 0)) * LDO + c0 + ((lid & 16) ? 8 : 0)) * 2;
    const uint32_t rstep = 16 * LDO * 2;

#pragma unroll
    for (int kt = 0; kt < 4; kt++) {
        const uint32_t ko = (uint32_t)kt * 32;
        uint32_t ah[2][4], al[2][4], bh[2][4], bl[2][4];
        ldsm4(ah[0], aA + ko);
        ldsm4(ah[1], aA + rstep + ko);
        ldsm4(al[0], aA + 128 + ko);
        ldsm4(al[1], aA + rstep + 128 + ko);
        const uint32_t bk = bA + (uint32_t)kt * rstep;
        ldsm4t(bh[0], bk);
        ldsm4t(bh[1], bk + 32);
        ldsm4t(bl[0], bk + 128);
        ldsm4t(bl[1], bk + 32 + 128);
        prod_all(c, ah[0], ah[1], al[0], al[1], bh, bl);
    }
}

// Register epilogue: X[row][col] = c (+ LIN: bB*B + aI on diag). Row-major [hi|lo].
template <bool LIN, bool GM>
static __device__ __forceinline__ void epilogue(
    float c[2][4][4], __nv_bfloat16* dst, const float* w, float* gout,
    int wid, int lid, float aI, float bB)
{
    const int g = lid >> 2, tg = lid & 3;
    const int r0 = (wid >> 1) * 32, c0 = (wid & 1) * 32;
#pragma unroll
    for (int m = 0; m < 2; m++) {
#pragma unroll
        for (int h = 0; h < 2; h++) {
            const int row = r0 + 16 * m + 8 * h + g;
#pragma unroll
            for (int j = 0; j < 4; j++) {
                const int col = c0 + 8 * j + 2 * tg;
                float x0 = c[m][j][2 * h], x1 = c[m][j][2 * h + 1];
                if (LIN) {
                    x0 += bB * getB(w, row, col);
                    x1 += bB * getB(w, row, col + 1);
                    if (col == row) x0 += aI;
                    if (col + 1 == row) x1 += aI;
                }
                if (GM) {
                    *reinterpret_cast<float2*>(gout + row * 64 + col) = make_float2(x0, x1);
                } else {
                    uint32_t hw, lw;
                    splitw(x0, x1, hw, lw);
                    *reinterpret_cast<uint32_t*>(dst + row * LDO + col) = hw;
                    *reinterpret_cast<uint32_t*>(dst + row * LDO + 64 + col) = lw;
                }
            }
        }
    }
}

__global__ void __launch_bounds__(128, 5)
SkewSymMatrixExp_kernel(const float* __restrict__ Svec, float* __restrict__ out)
{
    extern __shared__ char smem[];
    const uint32_t sb = smem_u32(smem);
    __nv_bfloat16* Xbuf  = reinterpret_cast<__nv_bfloat16*>(smem + SM_X);
    __nv_bfloat16* B2buf = reinterpret_cast<__nv_bfloat16*>(smem + SM_B2);
    float* w = reinterpret_cast<float*>(smem + SM_V);

    const int tid = threadIdx.x, wid = tid >> 5, lid = tid & 31;
    const float* v = Svec + (size_t)blockIdx.x * 2016;

    // ---- load scaled vector w = v/16 (coalesced)
    for (int n = tid; n < 2016; n += 128) w[n] = v[n] * 0.0625f;
    __syncthreads();

    // ---- initial X = split(B), row-major
    {
        const int r = tid >> 1;
        const int k0 = (tid & 1) * 32;
#pragma unroll 4
        for (int kk = k0; kk < k0 + 32; kk += 2) {
            float x0 = getB(w, r, kk), x1 = getB(w, r, kk + 1);
            uint32_t hw, lw;
            splitw(x0, x1, hw, lw);
            *reinterpret_cast<uint32_t*>(Xbuf + r * LDO + kk) = hw;
            *reinterpret_cast<uint32_t*>(Xbuf + r * LDO + 64 + kk) = lw;
        }
    }
    __syncthreads();

    // Taylor coeffs a_i = 1/(2i)!, b_i = 1/(2i+1)!
    const float A4 = 2.4801587e-5f, B4 = 2.7557319e-6f;
    const float A3 = 1.3888889e-3f, B3 = 1.9841270e-4f;
    const float A2 = 4.1666668e-2f, B2c = 8.3333333e-3f;
    const float A1 = 0.5f, B1 = 1.6666667e-1f;

    float c[2][4][4];

    // ---- step 0: B2 = B*B -> B2buf. Then Xbuf <- r4 = A4*I + B4*B.
    mm_compute(c, sb + SM_X, sb + SM_X, wid, lid);
    __syncthreads();
    epilogue<false, false>(c, B2buf, w, nullptr, wid, lid, 0.f, 0.f);
    {
        const int r = tid >> 1;
        const int k0 = (tid & 1) * 32;
#pragma unroll 4
        for (int kk = k0; kk < k0 + 32; kk += 2) {
            float x0 = B4 * getB(w, r, kk) + (kk == r ? A4 : 0.f);
            float x1 = B4 * getB(w, r, kk + 1) + (kk + 1 == r ? A4 : 0.f);
            uint32_t hw, lw;
            splitw(x0, x1, hw, lw);
            *reinterpret_cast<uint32_t*>(Xbuf + r * LDO + kk) = hw;
            *reinterpret_cast<uint32_t*>(Xbuf + r * LDO + 64 + kk) = lw;
        }
    }
    __syncthreads();

    // ---- chain steps 1..3: r <- a I + b B + B2*r
    const float av[3] = { A3, A2, A1 };
    const float bv[3] = { B3, B2c, B1 };
#pragma unroll 1
    for (int s = 0; s < 3; s++) {
        mm_compute(c, sb + SM_B2, sb + SM_X, wid, lid);
        __syncthreads();
        epilogue<true, false>(c, Xbuf, w, nullptr, wid, lid, av[s], bv[s]);
        __syncthreads();
    }

    // ---- step 4: P = I + B + B2*r1
    mm_compute(c, sb + SM_B2, sb + SM_X, wid, lid);
    __syncthreads();
    epilogue<true, false>(c, Xbuf, w, nullptr, wid, lid, 1.f, 1.f);
    __syncthreads();

    // ---- squarings 1..3: X <- X*X
#pragma unroll 1
    for (int s = 0; s < 3; s++) {
        mm_compute(c, sb + SM_X, sb + SM_X, wid, lid);
        __syncthreads();
        epilogue<false, false>(c, Xbuf, w, nullptr, wid, lid, 0.f, 0.f);
        __syncthreads();
    }

    // ---- squaring 4: straight to global
    mm_compute(c, sb + SM_X, sb + SM_X, wid, lid);
    epilogue<false, true>(c, Xbuf, w, out + (size_t)blockIdx.x * 4096,
                          wid, lid, 0.f, 0.f);
}

extern "C" void kernel_launch(void* const* d_in, const int* in_sizes, int n_in,
                              void* d_out, int out_size)
{
    const float* svec = (const float*)d_in[0];
    float* out = (float*)d_out;
    const int batch = in_sizes[0] / 2016;

    cudaFuncSetAttribute(SkewSymMatrixExp_kernel,
                         cudaFuncAttributeMaxDynamicSharedMemorySize, SMEM_BYTES);
    SkewSymMatrixExp_kernel<<<batch, 128, SMEM_BYTES>>>(svec, out);
}